// round 8
// baseline (speedup 1.0000x reference)
#include <cuda_runtime.h>
#include <cstdint>
#include <cstddef>

#define B_      64
#define LQ      1024
#define LK      1024
#define DH      64
#define QT      16
#define CHUNK   128
#define NCH     (LK / CHUNK)   // 8
#define NTHR    512
#define KSP     68             // k_s pitch: banks (4r+c)%32 -> conflict-free A-frag LDS
#define SCP     1028           // sc pitch: score STS banks 8c+r -> conflict-free
#define CAP     256            // compacted-gather capacity per row (overflow -> serial path)
#define TEMP_INV 0.125f
#define REMOVED  (-1.0e30f)
#define CUTV     (-1.0e29f)

// smem floats: k_s[128*68] (re-used as gather scratch: 16*2*CAP=8192 <= 8704) | sc[16*1028]
#define KS_FLOATS   (CHUNK * KSP)
#define SC_FLOATS   (QT * SCP)
#define SMEM_FLOATS (KS_FLOATS + SC_FLOATS)
#define SMEM_BYTES  (SMEM_FLOATS * 4)

__device__ int g_mask_kind;   // 0 = uint8/bool, 1 = int32, 2 = float32

__global__ void detect_mask_kernel(const unsigned char* __restrict__ m) {
    __shared__ int nz[4];
    int tid = threadIdx.x;
    if (tid < 4) nz[tid] = 0;
    __syncthreads();
    int ph = tid & 3;          // stride 512 is a multiple of 4 -> phase fixed per thread
    int c = 0;
    for (int i = tid; i < 8192; i += 512)
        if (m[i]) c++;
    if (c) atomicAdd(&nz[ph], c);
    __syncthreads();
    if (tid == 0) {
        int kind;
        if ((nz[1] | nz[2] | nz[3]) == 0)      kind = 1;  // int32
        else if (nz[0] == 0 && nz[3] > 0)      kind = 2;  // float32
        else                                   kind = 0;  // uint8 / bool
        g_mask_kind = kind;
    }
}

// Markidis truncation split: hi = x with low 13 mantissa bits cleared (valid tf32),
// lo = x - hi (exact, also a valid tf32 operand).
__device__ __forceinline__ float trunc_hi(float x) {
    return __uint_as_float(__float_as_uint(x) & 0xFFFFE000u);
}

__device__ __forceinline__ void mma_tf32(float& d0, float& d1, float& d2, float& d3,
                                         unsigned a0, unsigned a1, unsigned a2, unsigned a3,
                                         unsigned b0, unsigned b1) {
    asm("mma.sync.aligned.m16n8k8.row.col.f32.tf32.tf32.f32 "
        "{%0,%1,%2,%3}, {%4,%5,%6,%7}, {%8,%9}, {%0,%1,%2,%3};"
        : "+f"(d0), "+f"(d1), "+f"(d2), "+f"(d3)
        : "r"(a0), "r"(a1), "r"(a2), "r"(a3), "r"(b0), "r"(b1));
}

// --------------------------------------------------------------------------
// One CTA = 16 q-rows of one batch, 512 threads / 16 warps.
// GEMM: A = K (smem, scalar LDS), B = Q (16 fp32 regs/warp, split inline).
// Sparsemax (stateless Michelot) per warp, then ballot-compacted (p, j) list
// in smem -> batched V gather with 4-way MLP. Overflow (>CAP nonzeros) falls
// back to the serial shuffle path.
// --------------------------------------------------------------------------
extern "C" __global__ void __launch_bounds__(NTHR, 2)
sparse_attn_kernel(const float* __restrict__ q,
                   const float* __restrict__ k,
                   const float* __restrict__ v,
                   const void*  __restrict__ maskp,
                   float* __restrict__ out,
                   float* __restrict__ attn,
                   int write_attn)
{
    extern __shared__ float sm[];
    float* k_s = sm;                              // [CHUNK][KSP]; later gather scratch
    float* sc  = sm + KS_FLOATS;                  // [QT][SCP]

    const int tid  = threadIdx.x;
    const int w    = tid >> 5;
    const int lane = tid & 31;
    const int b    = blockIdx.y;
    const int q0   = blockIdx.x * QT;
    const int mkind = g_mask_kind;

    // ---- Q subtile (w>>3) as fp32 B-fragment values in registers ----
    float x0[8], x1[8];
    {
        const float* qb = q + ((size_t)(b * LQ + q0 + 8 * (w >> 3) + (lane >> 2))) * DH + (lane & 3);
        #pragma unroll
        for (int ks = 0; ks < 8; ++ks) {
            x0[ks] = qb[ks * 8]     * TEMP_INV;
            x1[ks] = qb[ks * 8 + 4] * TEMP_INV;
        }
    }
    const int kr0 = 16 * (w & 7);

    // ---- QK^T over 8 chunks of 128 K-rows ----
    for (int c = 0; c < NCH; ++c) {
        __syncthreads();
        #pragma unroll
        for (int it = 0; it < (CHUNK * 16) / NTHR; ++it) {
            int fi = tid + NTHR * it;
            int r  = fi >> 4;
            int d4 = fi & 15;
            const float4 kv = *(const float4*)(k + ((size_t)(b * LK + c * CHUNK + r)) * DH + 4 * d4);
            *(float4*)(k_s + r * KSP + 4 * d4) = kv;
        }
        __syncthreads();

        float d0 = 0.f, d1 = 0.f, d2 = 0.f, d3 = 0.f;
        const float* ap = k_s + (kr0 + (lane >> 2)) * KSP + (lane & 3);
        #pragma unroll
        for (int ks = 0; ks < 8; ++ks) {
            float a0f = ap[ks * 8];
            float a1f = ap[8 * KSP + ks * 8];
            float a2f = ap[ks * 8 + 4];
            float a3f = ap[8 * KSP + ks * 8 + 4];
            float h0 = trunc_hi(a0f), h1 = trunc_hi(a1f), h2 = trunc_hi(a2f), h3 = trunc_hi(a3f);
            unsigned ah0 = __float_as_uint(h0), ah1 = __float_as_uint(h1),
                     ah2 = __float_as_uint(h2), ah3 = __float_as_uint(h3);
            unsigned al0 = __float_as_uint(a0f - h0), al1 = __float_as_uint(a1f - h1),
                     al2 = __float_as_uint(a2f - h2), al3 = __float_as_uint(a3f - h3);
            float qh0f = trunc_hi(x0[ks]), qh1f = trunc_hi(x1[ks]);
            unsigned qh0 = __float_as_uint(qh0f), qh1 = __float_as_uint(qh1f);
            unsigned ql0 = __float_as_uint(x0[ks] - qh0f), ql1 = __float_as_uint(x1[ks] - qh1f);
            mma_tf32(d0, d1, d2, d3, ah0, ah1, ah2, ah3, ql0, ql1);
            mma_tf32(d0, d1, d2, d3, al0, al1, al2, al3, qh0, qh1);
            mma_tf32(d0, d1, d2, d3, ah0, ah1, ah2, ah3, qh0, qh1);
        }
        int kg = c * CHUNK + kr0 + (lane >> 2);
        int qc = 8 * (w >> 3) + 2 * (lane & 3);
        sc[qc * SCP + kg]           = d0;
        sc[(qc + 1) * SCP + kg]     = d1;
        sc[qc * SCP + kg + 8]       = d2;
        sc[(qc + 1) * SCP + kg + 8] = d3;
    }
    __syncthreads();

    // ---- mask pass, 16-byte vectorized ----
    {
        size_t mbase = ((size_t)b * LQ + q0) * LK;
        if (mkind == 0) {
            const uint4* m4 = (const uint4*)((const unsigned char*)maskp + mbase);
            #pragma unroll
            for (int it = 0; it < (QT * LK) / 16 / NTHR; ++it) {
                int idx  = tid + NTHR * it;
                uint4 u  = m4[idx];
                int base = idx * 16;
                float* srow = sc + (base >> 10) * SCP + (base & 1023);
                #pragma unroll
                for (int bt = 0; bt < 4; ++bt) {
                    unsigned uu = (&u.x)[bt];
                    if (uu & 0x000000FFu) srow[bt * 4 + 0] = REMOVED;
                    if (uu & 0x0000FF00u) srow[bt * 4 + 1] = REMOVED;
                    if (uu & 0x00FF0000u) srow[bt * 4 + 2] = REMOVED;
                    if (uu & 0xFF000000u) srow[bt * 4 + 3] = REMOVED;
                }
            }
        } else {   // int32 / float32: nonzero bits == true
            const uint4* m4 = (const uint4*)((const unsigned*)maskp + mbase);
            #pragma unroll
            for (int it = 0; it < (QT * LK) / 4 / NTHR; ++it) {
                int idx  = tid + NTHR * it;
                uint4 u  = m4[idx];
                int base = idx * 4;
                float* srow = sc + (base >> 10) * SCP + (base & 1023);
                if (u.x) srow[0] = REMOVED;
                if (u.y) srow[1] = REMOVED;
                if (u.z) srow[2] = REMOVED;
                if (u.w) srow[3] = REMOVED;
            }
        }
    }
    __syncthreads();   // also fences k_s re-use below (all GEMM reads done)

    // ---- sparsemax (warp w owns row w): stateless Michelot ----
    const float* zr = sc + w * SCP;
    float S = 0.0f; int C = 0;
    #pragma unroll
    for (int t4 = 0; t4 < 8; ++t4) {
        float4 zv = *(const float4*)(zr + 4 * lane + 128 * t4);
        if (zv.x > CUTV) { S += zv.x; C++; }
        if (zv.y > CUTV) { S += zv.y; C++; }
        if (zv.z > CUTV) { S += zv.z; C++; }
        if (zv.w > CUTV) { S += zv.w; C++; }
    }
    #pragma unroll
    for (int o = 16; o; o >>= 1) {
        S += __shfl_xor_sync(0xFFFFFFFFu, S, o);
        C += __shfl_xor_sync(0xFFFFFFFFu, C, o);
    }

    float tau;
    if (C > 0) {
        tau = (S - 1.0f) / (float)C;
        for (int iter = 0; iter < 64; ++iter) {
            float s2 = 0.0f; int c2 = 0;
            #pragma unroll
            for (int t4 = 0; t4 < 8; ++t4) {
                float4 zv = *(const float4*)(zr + 4 * lane + 128 * t4);
                if (zv.x > tau) { s2 += zv.x; c2++; }
                if (zv.y > tau) { s2 += zv.y; c2++; }
                if (zv.z > tau) { s2 += zv.z; c2++; }
                if (zv.w > tau) { s2 += zv.w; c2++; }
            }
            #pragma unroll
            for (int o = 16; o; o >>= 1) {
                s2 += __shfl_xor_sync(0xFFFFFFFFu, s2, o);
                c2 += __shfl_xor_sync(0xFFFFFFFFu, c2, o);
            }
            if (c2 == C) break;            // converged
            S = s2; C = c2;
            tau = (S - 1.0f) / (float)C;
        }
    } else {
        tau = 1.0e30f;                     // fully-masked row
    }

    // ---- probabilities -> attn (float4 stores) + ballot-compacted (p,j) list ----
    const float2* vb2 = (const float2*)(v + (size_t)b * LK * DH);
    float* cp = k_s + w * (2 * CAP);       // per-warp scratch (k_s is dead)
    float* arow = attn + ((size_t)(b * LQ + q0 + w)) * LK;
    const unsigned lt = (1u << lane) - 1u;
    float2 acc2 = make_float2(0.0f, 0.0f);
    int cnt = 0;

    #pragma unroll
    for (int tt = 0; tt < 8; ++tt) {
        const int j0 = 4 * lane + 128 * tt;
        float4 zv = *(const float4*)(zr + j0);
        float4 pv;
        pv.x = fmaxf(zv.x - tau, 0.0f);
        pv.y = fmaxf(zv.y - tau, 0.0f);
        pv.z = fmaxf(zv.z - tau, 0.0f);
        pv.w = fmaxf(zv.w - tau, 0.0f);
        if (write_attn) *(float4*)(arow + j0) = pv;

        unsigned bb0 = __ballot_sync(0xFFFFFFFFu, pv.x > 0.0f);
        unsigned bb1 = __ballot_sync(0xFFFFFFFFu, pv.y > 0.0f);
        unsigned bb2 = __ballot_sync(0xFFFFFFFFu, pv.z > 0.0f);
        unsigned bb3 = __ballot_sync(0xFFFFFFFFu, pv.w > 0.0f);
        int base0 = cnt;
        int base1 = base0 + __popc(bb0);
        int base2 = base1 + __popc(bb1);
        int base3 = base2 + __popc(bb2);
        cnt       = base3 + __popc(bb3);

        int ps;
        ps = base0 + __popc(bb0 & lt);
        if (pv.x > 0.0f && ps < CAP) { cp[2 * ps] = pv.x; cp[2 * ps + 1] = __int_as_float(j0); }
        ps = base1 + __popc(bb1 & lt);
        if (pv.y > 0.0f && ps < CAP) { cp[2 * ps] = pv.y; cp[2 * ps + 1] = __int_as_float(j0 + 1); }
        ps = base2 + __popc(bb2 & lt);
        if (pv.z > 0.0f && ps < CAP) { cp[2 * ps] = pv.z; cp[2 * ps + 1] = __int_as_float(j0 + 2); }
        ps = base3 + __popc(bb3 & lt);
        if (pv.w > 0.0f && ps < CAP) { cp[2 * ps] = pv.w; cp[2 * ps + 1] = __int_as_float(j0 + 3); }

        // overflow (support > CAP): serial fallback for the spilled entries
        if (cnt > CAP) {
            #pragma unroll
            for (int e = 0; e < 4; ++e) {
                float pe = (&pv.x)[e];
                unsigned bb = (e == 0) ? bb0 : (e == 1) ? bb1 : (e == 2) ? bb2 : bb3;
                int be     = (e == 0) ? base0 : (e == 1) ? base1 : (e == 2) ? base2 : base3;
                unsigned ovf = __ballot_sync(0xFFFFFFFFu,
                                             pe > 0.0f && (be + __popc(bb & lt)) >= CAP);
                while (ovf) {
                    int src = __ffs(ovf) - 1;
                    ovf &= ovf - 1;
                    float pj = __shfl_sync(0xFFFFFFFFu, pe, src);
                    int j = 4 * src + 128 * tt + e;
                    const float2 vv = vb2[j * 32 + lane];
                    acc2.x += pj * vv.x;
                    acc2.y += pj * vv.y;
                }
            }
        }
    }
    __syncwarp();

    // ---- batched V gather: 4 independent loads in flight ----
    {
        const int cn = cnt < CAP ? cnt : CAP;
        int i = 0;
        for (; i + 4 <= cn; i += 4) {
            float4 e0 = *(const float4*)(cp + 2 * i);       // p0 j0 p1 j1 (broadcast LDS)
            float4 e1 = *(const float4*)(cp + 2 * i + 4);   // p2 j2 p3 j3
            const float2 v0 = vb2[__float_as_int(e0.y) * 32 + lane];
            const float2 v1 = vb2[__float_as_int(e0.w) * 32 + lane];
            const float2 v2 = vb2[__float_as_int(e1.y) * 32 + lane];
            const float2 v3 = vb2[__float_as_int(e1.w) * 32 + lane];
            acc2.x += e0.x * v0.x;  acc2.y += e0.x * v0.y;
            acc2.x += e0.z * v1.x;  acc2.y += e0.z * v1.y;
            acc2.x += e1.x * v2.x;  acc2.y += e1.x * v2.y;
            acc2.x += e1.z * v3.x;  acc2.y += e1.z * v3.y;
        }
        for (; i < cn; ++i) {
            float p = cp[2 * i];
            int  j  = __float_as_int(cp[2 * i + 1]);
            const float2 vv = vb2[j * 32 + lane];
            acc2.x += p * vv.x;
            acc2.y += p * vv.y;
        }
    }

    *(float2*)(out + ((size_t)(b * LQ + q0 + w)) * DH + 2 * lane) = acc2;
}

// --------------------------------------------------------------------------
extern "C" void kernel_launch(void* const* d_in, const int* in_sizes, int n_in,
                              void* d_out, int out_size) {
    const float* q = (const float*)d_in[0];
    const float* k = (const float*)d_in[1];
    const float* v = (const float*)d_in[2];
    const void*  m = d_in[3];

    float* out = (float*)d_out;
    long long out_elems  = (long long)B_ * LQ * DH;
    long long attn_elems = (long long)B_ * LQ * LK;
    int write_attn = ((long long)out_size >= out_elems + attn_elems) ? 1 : 0;
    float* attn = out + (size_t)out_elems;

    detect_mask_kernel<<<1, 512>>>((const unsigned char*)m);

    cudaFuncSetAttribute(sparse_attn_kernel,
                         cudaFuncAttributeMaxDynamicSharedMemorySize, SMEM_BYTES);

    dim3 grid(LQ / QT, B_);
    sparse_attn_kernel<<<grid, NTHR, SMEM_BYTES>>>(q, k, v, m, out, attn, write_attn);
}

// round 10
// speedup vs baseline: 1.1572x; 1.1572x over previous
#include <cuda_runtime.h>
#include <cstdint>
#include <cstddef>

#define B_      64
#define LQ      1024
#define LK      1024
#define DH      64
#define QT      16
#define CHUNK   128
#define NCH     (LK / CHUNK)   // 8
#define NTHR    512
#define KP32    36             // K smem pitch in u32 units: bank=(36r+u)%32=(4r+u)%32=lane -> conflict-free
#define SCP     1028           // sc pitch: score STS conflict-free
#define CAPS    512            // sparsemax compact-list capacity (floats, per warp)
#define CAPG    256            // gather pair capacity (pairs, per warp)
#define TEMP_INV 0.125f
#define REMOVED  (-1.0e30f)
#define CUTV     (-1.0e29f)

// smem: khi[128*36 u32] kmid[128*36 u32] (=9216 floats; reused as 16x576 warp scratch) | sc[16*1028]
#define KS_FLOATS   (2 * CHUNK * KP32)     // 9216
#define SC_FLOATS   (QT * SCP)             // 16448
#define SMEM_FLOATS (KS_FLOATS + SC_FLOATS)
#define SMEM_BYTES  (SMEM_FLOATS * 4)
#define WSCR        576                    // per-warp scratch floats (16*576 = 9216)

__device__ int g_mask_kind;   // 0 = uint8/bool, 1 = int32, 2 = float32

__global__ void detect_mask_kernel(const unsigned char* __restrict__ m) {
    __shared__ int nz[4];
    int tid = threadIdx.x;
    if (tid < 4) nz[tid] = 0;
    __syncthreads();
    int ph = tid & 3;
    int c = 0;
    for (int i = tid; i < 8192; i += 512)
        if (m[i]) c++;
    if (c) atomicAdd(&nz[ph], c);
    __syncthreads();
    if (tid == 0) {
        int kind;
        if ((nz[1] | nz[2] | nz[3]) == 0)      kind = 1;  // int32
        else if (nz[0] == 0 && nz[3] > 0)      kind = 2;  // float32
        else                                   kind = 0;  // uint8 / bool
        g_mask_kind = kind;
    }
}

// pack two fp32 -> f16x2 (lo = x, hi = y)
__device__ __forceinline__ unsigned pack_h2(float x, float y) {
    unsigned r;
    asm("cvt.rn.f16x2.f32 %0, %1, %2;" : "=r"(r) : "f"(y), "f"(x));
    return r;
}
// unpack f16x2 -> two fp32
__device__ __forceinline__ void unpack_h2(unsigned p, float& x, float& y) {
    asm("{ .reg .f16 l, h; mov.b32 {l, h}, %2; cvt.f32.f16 %0, l; cvt.f32.f16 %1, h; }"
        : "=f"(x), "=f"(y) : "r"(p));
}

__device__ __forceinline__ void mma_f16(float& d0, float& d1, float& d2, float& d3,
                                        unsigned a0, unsigned a1, unsigned a2, unsigned a3,
                                        unsigned b0, unsigned b1) {
    asm("mma.sync.aligned.m16n8k16.row.col.f32.f16.f16.f32 "
        "{%0,%1,%2,%3}, {%4,%5,%6,%7}, {%8,%9}, {%0,%1,%2,%3};"
        : "+f"(d0), "+f"(d1), "+f"(d2), "+f"(d3)
        : "r"(a0), "r"(a1), "r"(a2), "r"(a3), "r"(b0), "r"(b1));
}

// --------------------------------------------------------------------------
// One CTA = 16 q-rows of one batch, 512 threads / 16 warps.
// QK^T: fp16x2 3-term compensated MMA (m16n8k16). K split hi/mid ONCE per
// chunk during staging; Q split once into 16 regs/warp. 12 MMAs/warp-chunk.
// Sparsemax: stateless Michelot first pass, then survivors compacted into
// per-warp smem list for cheap iterations. Gather: ballot-compacted (p,j)
// pairs, 4-way MLP batched V loads.
// --------------------------------------------------------------------------
extern "C" __global__ void __launch_bounds__(NTHR, 2)
sparse_attn_kernel(const float* __restrict__ q,
                   const float* __restrict__ k,
                   const float* __restrict__ v,
                   const void*  __restrict__ maskp,
                   float* __restrict__ out,
                   float* __restrict__ attn,
                   int write_attn)
{
    extern __shared__ float sm[];
    unsigned* khi_s  = (unsigned*)sm;             // [CHUNK][KP32] f16x2 (hi)
    unsigned* kmid_s = khi_s + CHUNK * KP32;      // [CHUNK][KP32] f16x2 (mid)
    float*    sc     = sm + KS_FLOATS;            // [QT][SCP]

    const int tid  = threadIdx.x;
    const int w    = tid >> 5;
    const int lane = tid & 31;
    const int b    = blockIdx.y;
    const int q0   = blockIdx.x * QT;
    const int mkind = g_mask_kind;

    // ---- Q subtile (w>>3) as f16x2 B fragments (hi + mid), 16 regs ----
    // B col-major 16x8: b0 = {B[2c][n], B[2c+1][n]}, b1 at k+8; n=lane/4, c=lane%4
    unsigned bh0[4], bh1[4], bm0[4], bm1[4];
    {
        const float* qb = q + ((size_t)(b * LQ + q0 + 8 * (w >> 3) + (lane >> 2))) * DH + 2 * (lane & 3);
        #pragma unroll
        for (int ks = 0; ks < 4; ++ks) {
            float2 p0 = *(const float2*)(qb + ks * 16);      // k = 2c, 2c+1
            float2 p1 = *(const float2*)(qb + ks * 16 + 8);  // k = 2c+8, 2c+9
            float f0 = p0.x * TEMP_INV, f1 = p0.y * TEMP_INV;
            float f2 = p1.x * TEMP_INV, f3 = p1.y * TEMP_INV;
            bh0[ks] = pack_h2(f0, f1);
            bh1[ks] = pack_h2(f2, f3);
            float h0, h1, h2, h3;
            unpack_h2(bh0[ks], h0, h1);
            unpack_h2(bh1[ks], h2, h3);
            bm0[ks] = pack_h2(f0 - h0, f1 - h1);
            bm1[ks] = pack_h2(f2 - h2, f3 - h3);
        }
    }
    const int kr0 = 16 * (w & 7);

    // ---- QK^T over 8 chunks of 128 K-rows ----
    for (int c = 0; c < NCH; ++c) {
        __syncthreads();
        // stage K chunk with fp16 hi/mid split (split computed ONCE per chunk)
        #pragma unroll
        for (int it = 0; it < (CHUNK * 16) / NTHR; ++it) {
            int fi = tid + NTHR * it;
            int r  = fi >> 4;
            int d4 = fi & 15;
            const float4 kv = *(const float4*)(k + ((size_t)(b * LK + c * CHUNK + r)) * DH + 4 * d4);
            unsigned hA = pack_h2(kv.x, kv.y);
            unsigned hB = pack_h2(kv.z, kv.w);
            float hx, hy, hz, hw;
            unpack_h2(hA, hx, hy);
            unpack_h2(hB, hz, hw);
            unsigned mA = pack_h2(kv.x - hx, kv.y - hy);
            unsigned mB = pack_h2(kv.z - hz, kv.w - hw);
            int u = r * KP32 + 2 * d4;
            khi_s[u]      = hA;  khi_s[u + 1]  = hB;
            kmid_s[u]     = mA;  kmid_s[u + 1] = mB;
        }
        __syncthreads();

        // A = K rows [kr0, kr0+16): a0={(r,2c),(r,2c+1)} a1=(r+8,..) a2=(r,2c+8..9) a3=(r+8,..)
        float d0 = 0.f, d1 = 0.f, d2 = 0.f, d3 = 0.f;
        const int au = (kr0 + (lane >> 2)) * KP32 + (lane & 3);
        #pragma unroll
        for (int ks = 0; ks < 4; ++ks) {
            int o = au + ks * 8;
            unsigned a0h = khi_s[o],               a1h = khi_s[o + 8 * KP32];
            unsigned a2h = khi_s[o + 4],           a3h = khi_s[o + 4 + 8 * KP32];
            unsigned a0m = kmid_s[o],              a1m = kmid_s[o + 8 * KP32];
            unsigned a2m = kmid_s[o + 4],          a3m = kmid_s[o + 4 + 8 * KP32];
            mma_f16(d0, d1, d2, d3, a0h, a1h, a2h, a3h, bm0[ks], bm1[ks]);  // hi*mid
            mma_f16(d0, d1, d2, d3, a0m, a1m, a2m, a3m, bh0[ks], bh1[ks]);  // mid*hi
            mma_f16(d0, d1, d2, d3, a0h, a1h, a2h, a3h, bh0[ks], bh1[ks]);  // hi*hi
        }
        // C 16x8: rows = k, cols = q
        int kg = c * CHUNK + kr0 + (lane >> 2);
        int qc = 8 * (w >> 3) + 2 * (lane & 3);
        sc[qc * SCP + kg]           = d0;
        sc[(qc + 1) * SCP + kg]     = d1;
        sc[qc * SCP + kg + 8]       = d2;
        sc[(qc + 1) * SCP + kg + 8] = d3;
    }
    __syncthreads();

    // ---- mask pass, 16-byte vectorized ----
    {
        size_t mbase = ((size_t)b * LQ + q0) * LK;
        if (mkind == 0) {
            const uint4* m4 = (const uint4*)((const unsigned char*)maskp + mbase);
            #pragma unroll
            for (int it = 0; it < (QT * LK) / 16 / NTHR; ++it) {
                int idx  = tid + NTHR * it;
                uint4 u  = m4[idx];
                int base = idx * 16;
                float* srow = sc + (base >> 10) * SCP + (base & 1023);
                #pragma unroll
                for (int bt = 0; bt < 4; ++bt) {
                    unsigned uu = (&u.x)[bt];
                    if (uu & 0x000000FFu) srow[bt * 4 + 0] = REMOVED;
                    if (uu & 0x0000FF00u) srow[bt * 4 + 1] = REMOVED;
                    if (uu & 0x00FF0000u) srow[bt * 4 + 2] = REMOVED;
                    if (uu & 0xFF000000u) srow[bt * 4 + 3] = REMOVED;
                }
            }
        } else {
            const uint4* m4 = (const uint4*)((const unsigned*)maskp + mbase);
            #pragma unroll
            for (int it = 0; it < (QT * LK) / 4 / NTHR; ++it) {
                int idx  = tid + NTHR * it;
                uint4 u  = m4[idx];
                int base = idx * 4;
                float* srow = sc + (base >> 10) * SCP + (base & 1023);
                if (u.x) srow[0] = REMOVED;
                if (u.y) srow[1] = REMOVED;
                if (u.z) srow[2] = REMOVED;
                if (u.w) srow[3] = REMOVED;
            }
        }
    }
    __syncthreads();   // also fences k_s scratch reuse (GEMM reads done)

    // ---- sparsemax (warp w owns row w): Michelot with survivor compaction ----
    const float* zr = sc + w * SCP;
    float* wsc = sm + w * WSCR;            // per-warp scratch in dead K region
    const unsigned lt = (1u << lane) - 1u;

    float S = 0.0f; int Cl = 0;
    #pragma unroll
    for (int t4 = 0; t4 < 8; ++t4) {
        float4 zv = *(const float4*)(zr + 4 * lane + 128 * t4);
        if (zv.x > CUTV) { S += zv.x; Cl++; }
        if (zv.y > CUTV) { S += zv.y; Cl++; }
        if (zv.z > CUTV) { S += zv.z; Cl++; }
        if (zv.w > CUTV) { S += zv.w; Cl++; }
    }
    #pragma unroll
    for (int o = 16; o; o >>= 1) S += __shfl_xor_sync(0xFFFFFFFFu, S, o);
    int C = __reduce_add_sync(0xFFFFFFFFu, Cl);

    float tau;
    if (C > 0) {
        tau = (S - 1.0f) / (float)C;
        // compacting scan with tau0: survivors -> wsc (support set is subset forever)
        float s2 = 0.0f; int c2l = 0; int cnt = 0;
        #pragma unroll
        for (int t4 = 0; t4 < 8; ++t4) {
            float4 zv = *(const float4*)(zr + 4 * lane + 128 * t4);
            #pragma unroll
            for (int e = 0; e < 4; ++e) {
                float ze = (&zv.x)[e];
                bool a = ze > tau;
                unsigned bb = __ballot_sync(0xFFFFFFFFu, a);
                if (a) {
                    int ps = cnt + __popc(bb & lt);
                    if (ps < CAPS) wsc[ps] = ze;
                    s2 += ze; c2l++;
                }
                cnt += __popc(bb);
            }
        }
        int c2 = __reduce_add_sync(0xFFFFFFFFu, c2l);
        #pragma unroll
        for (int o = 16; o; o >>= 1) s2 += __shfl_xor_sync(0xFFFFFFFFu, s2, o);

        if (c2 != C) {
            if (cnt <= CAPS) {
                __syncwarp();
                S = s2; C = c2;
                tau = (S - 1.0f) / (float)C;
                for (int iter = 0; iter < 64; ++iter) {
                    float s3 = 0.0f; int c3l = 0;
                    for (int i = lane; i < cnt; i += 32) {
                        float z3 = wsc[i];
                        if (z3 > tau) { s3 += z3; c3l++; }
                    }
                    int c3 = __reduce_add_sync(0xFFFFFFFFu, c3l);
                    #pragma unroll
                    for (int o = 16; o; o >>= 1) s3 += __shfl_xor_sync(0xFFFFFFFFu, s3, o);
                    if (c3 == C) break;
                    S = s3; C = c3;
                    tau = (S - 1.0f) / (float)C;
                }
            } else {
                // stateless fallback (huge support)
                S = s2; C = c2;
                tau = (S - 1.0f) / (float)C;
                for (int iter = 0; iter < 64; ++iter) {
                    float s3 = 0.0f; int c3l = 0;
                    #pragma unroll
                    for (int t4 = 0; t4 < 8; ++t4) {
                        float4 zv = *(const float4*)(zr + 4 * lane + 128 * t4);
                        if (zv.x > tau) { s3 += zv.x; c3l++; }
                        if (zv.y > tau) { s3 += zv.y; c3l++; }
                        if (zv.z > tau) { s3 += zv.z; c3l++; }
                        if (zv.w > tau) { s3 += zv.w; c3l++; }
                    }
                    int c3 = __reduce_add_sync(0xFFFFFFFFu, c3l);
                    #pragma unroll
                    for (int o = 16; o; o >>= 1) s3 += __shfl_xor_sync(0xFFFFFFFFu, s3, o);
                    if (c3 == C) break;
                    S = s3; C = c3;
                    tau = (S - 1.0f) / (float)C;
                }
            }
        }
    } else {
        tau = 1.0e30f;                     // fully-masked row
    }
    __syncwarp();

    // ---- probabilities -> attn (float4 stores) + ballot-compacted (p,j) pairs ----
    const float2* vb2 = (const float2*)(v + (size_t)b * LK * DH);
    float* cp = wsc;                       // reuse scratch for (p, j) pairs
    float* arow = attn + ((size_t)(b * LQ + q0 + w)) * LK;
    float2 acc2 = make_float2(0.0f, 0.0f);
    int cnt = 0;

    #pragma unroll
    for (int tt = 0; tt < 8; ++tt) {
        const int j0 = 4 * lane + 128 * tt;
        float4 zv = *(const float4*)(zr + j0);
        float4 pv;
        pv.x = fmaxf(zv.x - tau, 0.0f);
        pv.y = fmaxf(zv.y - tau, 0.0f);
        pv.z = fmaxf(zv.z - tau, 0.0f);
        pv.w = fmaxf(zv.w - tau, 0.0f);
        if (write_attn) *(float4*)(arow + j0) = pv;

        unsigned bb0 = __ballot_sync(0xFFFFFFFFu, pv.x > 0.0f);
        unsigned bb1 = __ballot_sync(0xFFFFFFFFu, pv.y > 0.0f);
        unsigned bb2 = __ballot_sync(0xFFFFFFFFu, pv.z > 0.0f);
        unsigned bb3 = __ballot_sync(0xFFFFFFFFu, pv.w > 0.0f);
        int base0 = cnt;
        int base1 = base0 + __popc(bb0);
        int base2 = base1 + __popc(bb1);
        int base3 = base2 + __popc(bb2);
        cnt       = base3 + __popc(bb3);

        int ps;
        ps = base0 + __popc(bb0 & lt);
        if (pv.x > 0.0f && ps < CAPG) { cp[2 * ps] = pv.x; cp[2 * ps + 1] = __int_as_float(j0); }
        ps = base1 + __popc(bb1 & lt);
        if (pv.y > 0.0f && ps < CAPG) { cp[2 * ps] = pv.y; cp[2 * ps + 1] = __int_as_float(j0 + 1); }
        ps = base2 + __popc(bb2 & lt);
        if (pv.z > 0.0f && ps < CAPG) { cp[2 * ps] = pv.z; cp[2 * ps + 1] = __int_as_float(j0 + 2); }
        ps = base3 + __popc(bb3 & lt);
        if (pv.w > 0.0f && ps < CAPG) { cp[2 * ps] = pv.w; cp[2 * ps + 1] = __int_as_float(j0 + 3); }

        // overflow (support > CAPG): serial fallback for spilled entries
        if (cnt > CAPG) {
            #pragma unroll
            for (int e = 0; e < 4; ++e) {
                float pe = (&pv.x)[e];
                unsigned bb = (e == 0) ? bb0 : (e == 1) ? bb1 : (e == 2) ? bb2 : bb3;
                int be     = (e == 0) ? base0 : (e == 1) ? base1 : (e == 2) ? base2 : base3;
                unsigned ovf = __ballot_sync(0xFFFFFFFFu,
                                             pe > 0.0f && (be + __popc(bb & lt)) >= CAPG);
                while (ovf) {
                    int src = __ffs(ovf) - 1;
                    ovf &= ovf - 1;
                    float pj = __shfl_sync(0xFFFFFFFFu, pe, src);
                    int j = 4 * src + 128 * tt + e;
                    const float2 vv = vb2[j * 32 + lane];
                    acc2.x += pj * vv.x;
                    acc2.y += pj * vv.y;
                }
            }
        }
    }
    __syncwarp();

    // ---- batched V gather: 4 independent loads in flight ----
    {
        const int cn = cnt < CAPG ? cnt : CAPG;
        int i = 0;
        for (; i + 4 <= cn; i += 4) {
            float4 e0 = *(const float4*)(cp + 2 * i);
            float4 e1 = *(const float4*)(cp + 2 * i + 4);
            const float2 v0 = vb2[__float_as_int(e0.y) * 32 + lane];
            const float2 v1 = vb2[__float_as_int(e0.w) * 32 + lane];
            const float2 v2 = vb2[__float_as_int(e1.y) * 32 + lane];
            const float2 v3 = vb2[__float_as_int(e1.w) * 32 + lane];
            acc2.x += e0.x * v0.x;  acc2.y += e0.x * v0.y;
            acc2.x += e0.z * v1.x;  acc2.y += e0.z * v1.y;
            acc2.x += e1.x * v2.x;  acc2.y += e1.x * v2.y;
            acc2.x += e1.z * v3.x;  acc2.y += e1.z * v3.y;
        }
        for (; i < cn; ++i) {
            float p = cp[2 * i];
            int  j  = __float_as_int(cp[2 * i + 1]);
            const float2 vv = vb2[j * 32 + lane];
            acc2.x += p * vv.x;
            acc2.y += p * vv.y;
        }
    }

    *(float2*)(out + ((size_t)(b * LQ + q0 + w)) * DH + 2 * lane) = acc2;
}

// --------------------------------------------------------------------------
extern "C" void kernel_launch(void* const* d_in, const int* in_sizes, int n_in,
                              void* d_out, int out_size) {
    const float* q = (const float*)d_in[0];
    const float* k = (const float*)d_in[1];
    const float* v = (const float*)d_in[2];
    const void*  m = d_in[3];

    float* out = (float*)d_out;
    long long out_elems  = (long long)B_ * LQ * DH;
    long long attn_elems = (long long)B_ * LQ * LK;
    int write_attn = ((long long)out_size >= out_elems + attn_elems) ? 1 : 0;
    float* attn = out + (size_t)out_elems;

    detect_mask_kernel<<<1, 512>>>((const unsigned char*)m);

    cudaFuncSetAttribute(sparse_attn_kernel,
                         cudaFuncAttributeMaxDynamicSharedMemorySize, SMEM_BYTES);

    dim3 grid(LQ / QT, B_);
    sparse_attn_kernel<<<grid, NTHR, SMEM_BYTES>>>(q, k, v, m, out, attn, write_attn);
}